// round 7
// baseline (speedup 1.0000x reference)
#include <cuda_runtime.h>
#include <math.h>
#include <stdint.h>

#define B 4
#define T 4096
#define S 4096
#define E 512
#define H 64
#define RR 16
#define QSCALE 0.18033688011112042

typedef unsigned long long u64;

// ------------------ device scratch ------------------
__device__ float g_c, g_r;
__device__ float g_V[RR * 64];
__device__ float g_ut[B * RR * T];   // T_m(u_t), t contiguous (t-pairs = natural u64)
__device__ float g_k[B * S * H];
__device__ float g_v[B * S * H];
__device__ float g_P[B * RR * S];
__device__ float g_d4[4][B * S];
__device__ float g_rd[B * S];
__device__ float g_acc[8][B * T * H];

// ------------------ helpers ------------------
__device__ __forceinline__ void ffma2(u64& d, u64 a, u64 b) {
    asm("fma.rn.f32x2 %0, %1, %2, %0;" : "+l"(d) : "l"(a), "l"(b));
}
__device__ __forceinline__ u64 pk2(float x, float y) {
    u64 r; asm("mov.b64 %0, {%1,%2};" : "=l"(r) : "f"(x), "f"(y)); return r;
}
__device__ __forceinline__ float2 up2(u64 v) {
    float2 r; asm("mov.b64 {%0,%1}, %2;" : "=f"(r.x), "=f"(r.y) : "l"(v)); return r;
}
__device__ __forceinline__ float ex2f(float x) {
    float y; asm("ex2.approx.ftz.f32 %0, %1;" : "=f"(y) : "f"(x)); return y;
}

// ------------------ tiny prep ------------------
__global__ __launch_bounds__(1024) void minmax_kernel(const float* __restrict__ x) {
    __shared__ float smn[1024], smx[1024];
    int tid = threadIdx.x;
    float mn = 1e30f, mx = -1e30f;
    for (int i = tid; i < B * T; i += 1024) {
        float v = x[i]; mn = fminf(mn, v); mx = fmaxf(mx, v);
    }
    smn[tid] = mn; smx[tid] = mx; __syncthreads();
    for (int o = 512; o > 0; o >>= 1) {
        if (tid < o) { smn[tid] = fminf(smn[tid], smn[tid+o]); smx[tid] = fmaxf(smx[tid], smx[tid+o]); }
        __syncthreads();
    }
    if (tid == 0) { g_c = 0.5f*(smn[0]+smx[0]); g_r = 0.5f*(smx[0]-smn[0]) + 1e-6f; }
}

__global__ void coef_kernel(const float* __restrict__ qw, const float* __restrict__ qb) {
    int h = threadIdx.x;
    double c = (double)g_c, r = (double)g_r;
    double f[RR];
    for (int j = 0; j < RR; j++) {
        double th = 3.14159265358979323846 * (j + 0.5) / RR;
        f[j] = QSCALE * tanh((double)qw[h] * (c + r*cos(th)) + (double)qb[h]);
    }
    for (int m = 0; m < RR; m++) {
        double a = 0.0;
        for (int j = 0; j < RR; j++) a += f[j] * cos(3.14159265358979323846 * m * (j+0.5) / RR);
        a *= (m == 0 ? 1.0 : 2.0) / RR;
        g_V[m * 64 + h] = (float)a;
    }
}

__global__ __launch_bounds__(256) void u_prep(const float* __restrict__ x) {
    int i = blockIdx.x * 256 + threadIdx.x;
    int b = i >> 12, t = i & 4095;
    float u = (x[i] - g_c) / g_r;
    float tm2 = 1.0f, tm1 = u;
    g_ut[(b*RR+0)*T + t] = 1.0f;
    g_ut[(b*RR+1)*T + t] = u;
#pragma unroll
    for (int m = 2; m < RR; m++) {
        float tc = 2.0f*u*tm1 - tm2;
        g_ut[(b*RR+m)*T + t] = tc;
        tm2 = tm1; tm1 = tc;
    }
}

// ======================= kv kernel =======================
// block: 64 rows x 128 cols (k|v). 256 thr = 8 warps.
// warp wr: row-pairs 4wr..4wr+3 (8 rows); lane l: cols 4l..4l+3.
// a = row-pair u64 (warp-broadcast), b = col-dup u64 (lane-contiguous 32B).
#define KV_EI 0            // [64 e][36] u64 (32 rp + pad)
#define KV_WD 2304         // [64 e][130] u64 (128 c + pad)
#define KV_SMEM ((2304 + 64*130) * 8)

__global__ __launch_bounds__(256, 2) void kv_pk(const float* __restrict__ emb,
                                                const float* __restrict__ kw,
                                                const float* __restrict__ kb,
                                                const float* __restrict__ vw) {
    extern __shared__ __align__(16) u64 sm8[];
    const int r0 = blockIdx.x * 64;
    const int tid = threadIdx.x;
    const int wr = tid >> 5, l = tid & 31;

    u64 acc[4][4] = {};

    for (int e0 = 0; e0 < E; e0 += 64) {
        __syncthreads();
        // stage ei[e][rp] = (emb[2rp, e], emb[2rp+1, e])
#pragma unroll
        for (int k = 0; k < 2; k++) {
            int idx = tid + k * 256;
            int rp = idx >> 4, eg = (idx & 15) * 4;
            float4 v0 = *(const float4*)(emb + (size_t)(r0 + 2*rp) * E + e0 + eg);
            float4 v1 = *(const float4*)(emb + (size_t)(r0 + 2*rp + 1) * E + e0 + eg);
            sm8[KV_EI + (eg+0)*36 + rp] = pk2(v0.x, v1.x);
            sm8[KV_EI + (eg+1)*36 + rp] = pk2(v0.y, v1.y);
            sm8[KV_EI + (eg+2)*36 + rp] = pk2(v0.z, v1.z);
            sm8[KV_EI + (eg+3)*36 + rp] = pk2(v0.w, v1.w);
        }
        // stage wdup[e][c] = (w[c,e], w[c,e])
#pragma unroll
        for (int k = 0; k < 8; k++) {
            int idx = tid + k * 256;
            int c = idx >> 4, eg = (idx & 15) * 4;
            const float* w = (c < 64) ? (kw + (size_t)c * E) : (vw + (size_t)(c - 64) * E);
            float4 v = *(const float4*)(w + e0 + eg);
            sm8[KV_WD + (eg+0)*130 + c] = pk2(v.x, v.x);
            sm8[KV_WD + (eg+1)*130 + c] = pk2(v.y, v.y);
            sm8[KV_WD + (eg+2)*130 + c] = pk2(v.z, v.z);
            sm8[KV_WD + (eg+3)*130 + c] = pk2(v.w, v.w);
        }
        __syncthreads();
#pragma unroll 8
        for (int e = 0; e < 64; e++) {
            ulonglong2 a01 = *(const ulonglong2*)(sm8 + KV_EI + e*36 + 4*wr);
            ulonglong2 a23 = *(const ulonglong2*)(sm8 + KV_EI + e*36 + 4*wr + 2);
            u64 ar[4] = {a01.x, a01.y, a23.x, a23.y};
            ulonglong2 b01 = *(const ulonglong2*)(sm8 + KV_WD + e*130 + 4*l);
            ulonglong2 b23 = *(const ulonglong2*)(sm8 + KV_WD + e*130 + 4*l + 2);
            u64 br[4] = {b01.x, b01.y, b23.x, b23.y};
#pragma unroll
            for (int j = 0; j < 4; j++)
#pragma unroll
                for (int c = 0; c < 4; c++) ffma2(acc[j][c], ar[j], br[c]);
        }
    }
    // epilogue: rows r0+8wr+2j+half, cols 4l..4l+3
#pragma unroll
    for (int j = 0; j < 4; j++) {
        float2 vc[4];
#pragma unroll
        for (int c = 0; c < 4; c++) vc[c] = up2(acc[j][c]);
        int r = r0 + 8*wr + 2*j;
        if (l < 16) {
            float4 o0, o1;
            o0.x = tanhf(vc[0].x + kb[4*l+0]); o1.x = tanhf(vc[0].y + kb[4*l+0]);
            o0.y = tanhf(vc[1].x + kb[4*l+1]); o1.y = tanhf(vc[1].y + kb[4*l+1]);
            o0.z = tanhf(vc[2].x + kb[4*l+2]); o1.z = tanhf(vc[2].y + kb[4*l+2]);
            o0.w = tanhf(vc[3].x + kb[4*l+3]); o1.w = tanhf(vc[3].y + kb[4*l+3]);
            *(float4*)(g_k + (size_t)r * H + 4*l) = o0;
            *(float4*)(g_k + (size_t)(r+1) * H + 4*l) = o1;
        } else {
            float4 o0, o1;
            o0.x = tanhf(vc[0].x); o1.x = tanhf(vc[0].y);
            o0.y = tanhf(vc[1].x); o1.y = tanhf(vc[1].y);
            o0.z = tanhf(vc[2].x); o1.z = tanhf(vc[2].y);
            o0.w = tanhf(vc[3].x); o1.w = tanhf(vc[3].y);
            *(float4*)(g_v + (size_t)r * H + 4*l - 64) = o0;
            *(float4*)(g_v + (size_t)(r+1) * H + 4*l - 64) = o1;
        }
    }
}

// ------------------ P[b][m][s] = sum_h V[m][h] k[b][s][h] ------------------
__global__ __launch_bounds__(128) void p_prep() {
    __shared__ float Vs[RR * 64];
    __shared__ float ks[128][68];
    const int b = blockIdx.y, s0 = blockIdx.x * 128, tid = threadIdx.x;
    for (int i = tid; i < RR * 64; i += 128) Vs[i] = g_V[i];
    for (int i = tid; i < 128 * 16; i += 128) {
        int s = i >> 4, h4 = (i & 15) * 4;
        *(float4*)&ks[s][h4] = *(const float4*)(g_k + ((size_t)(b*S + s0 + s)) * H + h4);
    }
    __syncthreads();
    float kr[64];
#pragma unroll
    for (int h = 0; h < 64; h++) kr[h] = ks[tid][h];
#pragma unroll
    for (int m = 0; m < RR; m++) {
        float a = 0.0f;
#pragma unroll
        for (int h = 0; h < 64; h++) a += Vs[m * 64 + h] * kr[h];
        g_P[(b*RR + m) * S + s0 + tid] = a;
    }
}

// ======================= denom kernel =======================
// block: 64 s x 1024 t. 256 thr. warp wr: t-pairs 64wr.., lane l: s=2l,2l+1.
// a = U t-pair (broadcast), b = P dup pair (lane LDS.128). No syncs in main loop.
#define D_UT 0            // [16 m][516] u64 (512 tp + pad)
#define D_PD 8256         // [16 m][66] u64
#define D_U64 9312
#define D_SMEM (9312 * 8 + 256)

__global__ __launch_bounds__(256, 2) void denom_pk() {
    extern __shared__ __align__(16) u64 sm8[];
    float* dsh = (float*)(sm8 + D_U64);
    const int b = blockIdx.z, tq = blockIdx.y, sb = blockIdx.x * 64;
    const int t0 = tq * 1024;
    const int tid = threadIdx.x;
    const int wr = tid >> 5, l = tid & 31;

#pragma unroll
    for (int k = 0; k < 32; k++) {
        int idx = tid + k * 256;
        int m = idx >> 9, tp = idx & 511;
        sm8[D_UT + m*516 + tp] = ((const u64*)(g_ut + (size_t)(b*RR + m)*T + t0))[tp];
    }
#pragma unroll
    for (int k = 0; k < 4; k++) {
        int idx = tid + k * 256;
        int m = idx >> 6, s = idx & 63;
        float p = g_P[(b*RR + m)*S + sb + s];
        sm8[D_PD + m*66 + s] = pk2(p, p);
    }
    if (tid < 64) dsh[tid] = 0.0f;
    __syncthreads();

    float ds0 = 0.0f, ds1 = 0.0f;
    for (int it = 0; it < 8; it++) {
        const int tpb = 64*wr + 8*it;
        u64 lac[8][2] = {};
#pragma unroll
        for (int m = 0; m < RR; m++) {
            const u64* ap = sm8 + D_UT + m*516 + tpb;
            ulonglong2 a01 = *(const ulonglong2*)(ap + 0);
            ulonglong2 a23 = *(const ulonglong2*)(ap + 2);
            ulonglong2 a45 = *(const ulonglong2*)(ap + 4);
            ulonglong2 a67 = *(const ulonglong2*)(ap + 6);
            u64 ar[8] = {a01.x, a01.y, a23.x, a23.y, a45.x, a45.y, a67.x, a67.y};
            ulonglong2 bb = *(const ulonglong2*)(sm8 + D_PD + m*66 + 2*l);
#pragma unroll
            for (int j = 0; j < 8; j++) {
                ffma2(lac[j][0], ar[j], bb.x);
                ffma2(lac[j][1], ar[j], bb.y);
            }
        }
#pragma unroll
        for (int j = 0; j < 8; j++) {
            float2 f0 = up2(lac[j][0]);
            float2 f1 = up2(lac[j][1]);
            ds0 += ex2f(f0.x) + ex2f(f0.y);
            ds1 += ex2f(f1.x) + ex2f(f1.y);
        }
    }
    atomicAdd(&dsh[2*l], ds0);
    atomicAdd(&dsh[2*l+1], ds1);
    __syncthreads();
    if (tid < 64) g_d4[tq][b*S + sb + tid] = dsh[tid];
}

__global__ __launch_bounds__(256) void rd_prep() {
    int i = blockIdx.x * 256 + threadIdx.x;
    g_rd[i] = 1.0f / (g_d4[0][i] + g_d4[1][i] + g_d4[2][i] + g_d4[3][i]);
}

// ======================= out kernel =======================
// block: 128 t x 512 s (8 chunks of 64). 256 thr = 8 warps.
// warp wr owns t = 16wr..16wr+15 (t-pairs 8wr..8wr+7) for BOTH stages (warp-private W).
// stage1: a = U t-pair (bcast), b = P dup (lane s=2l,2l+1) -> W to smem (syncwarp only).
// stage2: a = W t-pair (bcast), b = v dup (lane h=2l,2l+1).
#define O_UT 0            // [16 m][66] u64
#define O_PD 1056         // [16 m][66] u64
#define O_WT 2112         // [64 s][66] u64 (t-pairs)
#define O_VD 6336         // [64 s][66] u64 (h dup)
#define O_U64 10560
#define O_SMEM (10560 * 8 + 256)

__global__ __launch_bounds__(256, 2) void out_pk() {
    extern __shared__ __align__(16) u64 sm8[];
    float* rds = (float*)(sm8 + O_U64);
    const int b = blockIdx.z, ss = blockIdx.y, tb0 = blockIdx.x * 128;
    const int tid = threadIdx.x;
    const int wr = tid >> 5, l = tid & 31;

#pragma unroll
    for (int k = 0; k < 4; k++) {
        int idx = tid + k * 256;
        int m = idx >> 6, tp = idx & 63;
        sm8[O_UT + m*66 + tp] = ((const u64*)(g_ut + (size_t)(b*RR + m)*T + tb0))[tp];
    }

    u64 oacc[8][2] = {};

    for (int st = 0; st < 8; st++) {
        const int sb = ss * 512 + st * 64;
        if (st) __syncthreads();   // protect previous chunk's reads
#pragma unroll
        for (int k = 0; k < 4; k++) {
            int idx = tid + k * 256;
            int m = idx >> 6, s = idx & 63;
            float p = g_P[(b*RR + m)*S + sb + s];
            sm8[O_PD + m*66 + s] = pk2(p, p);
        }
#pragma unroll
        for (int k = 0; k < 4; k++) {
            int idx = tid + k * 256;
            int s = idx >> 4, h4 = (idx & 15) * 4;
            float4 v = *(const float4*)(g_v + (size_t)(b*S + sb + s) * H + h4);
            sm8[O_VD + s*66 + h4+0] = pk2(v.x, v.x);
            sm8[O_VD + s*66 + h4+1] = pk2(v.y, v.y);
            sm8[O_VD + s*66 + h4+2] = pk2(v.z, v.z);
            sm8[O_VD + s*66 + h4+3] = pk2(v.w, v.w);
        }
        if (tid < 64) rds[tid] = g_rd[b*S + sb + tid];
        __syncthreads();

        // ---- stage 1: L for (16 t of this warp) x (s = 2l, 2l+1) ----
        u64 lac[8][2] = {};
#pragma unroll
        for (int m = 0; m < RR; m++) {
            const u64* ap = sm8 + O_UT + m*66 + 8*wr;
            ulonglong2 a01 = *(const ulonglong2*)(ap + 0);
            ulonglong2 a23 = *(const ulonglong2*)(ap + 2);
            ulonglong2 a45 = *(const ulonglong2*)(ap + 4);
            ulonglong2 a67 = *(const ulonglong2*)(ap + 6);
            u64 ar[8] = {a01.x, a01.y, a23.x, a23.y, a45.x, a45.y, a67.x, a67.y};
            ulonglong2 bb = *(const ulonglong2*)(sm8 + O_PD + m*66 + 2*l);
#pragma unroll
            for (int j = 0; j < 8; j++) {
                ffma2(lac[j][0], ar[j], bb.x);
                ffma2(lac[j][1], ar[j], bb.y);
            }
        }
        {
            float rs0 = rds[2*l], rs1 = rds[2*l+1];
#pragma unroll
            for (int j = 0; j < 8; j++) {
                float2 f0 = up2(lac[j][0]);
                float2 f1 = up2(lac[j][1]);
                sm8[O_WT + (2*l  )*66 + 8*wr + j] = pk2(ex2f(f0.x)*rs0, ex2f(f0.y)*rs0);
                sm8[O_WT + (2*l+1)*66 + 8*wr + j] = pk2(ex2f(f1.x)*rs1, ex2f(f1.y)*rs1);
            }
        }
        __syncwarp();

        // ---- stage 2: oacc[t-pair][h] += W[t-pair, s] * v[s, h] ----
#pragma unroll 4
        for (int s = 0; s < 64; s++) {
            const u64* ap = sm8 + O_WT + s*66 + 8*wr;
            ulonglong2 a01 = *(const ulonglong2*)(ap + 0);
            ulonglong2 a23 = *(const ulonglong2*)(ap + 2);
            ulonglong2 a45 = *(const ulonglong2*)(ap + 4);
            ulonglong2 a67 = *(const ulonglong2*)(ap + 6);
            u64 ar[8] = {a01.x, a01.y, a23.x, a23.y, a45.x, a45.y, a67.x, a67.y};
            ulonglong2 bv = *(const ulonglong2*)(sm8 + O_VD + s*66 + 2*l);
#pragma unroll
            for (int j = 0; j < 8; j++) {
                ffma2(oacc[j][0], ar[j], bv.x);
                ffma2(oacc[j][1], ar[j], bv.y);
            }
        }
    }

    // writeback: oacc[j][hb] halves = (out[t_even], out[t_odd]) at h = 2l+hb
#pragma unroll
    for (int j = 0; j < 8; j++) {
        float2 e0 = up2(oacc[j][0]);
        float2 e1 = up2(oacc[j][1]);
        size_t t0 = (size_t)(b*T) + tb0 + 16*wr + 2*j;
        *(float2*)&g_acc[ss][t0 * H + 2*l]       = make_float2(e0.x, e1.x);
        *(float2*)&g_acc[ss][(t0 + 1) * H + 2*l] = make_float2(e0.y, e1.y);
    }
}

// ------------------ final epilogue ------------------
__global__ __launch_bounds__(256) void final_ep(const float* __restrict__ pw,
                                                const float* __restrict__ pb,
                                                float* __restrict__ out) {
    __shared__ float red[64][5];
    __shared__ float pws[64];
    const int tid = threadIdx.x;
    if (tid < 64) pws[tid] = pw[tid];
    __syncthreads();
    const size_t bt0 = (size_t)blockIdx.x * 64;
    const int tl = tid >> 2, hq = tid & 3;
    const size_t base = (bt0 + tl) * H + hq * 16;
    float p = 0.0f;
#pragma unroll
    for (int h = 0; h < 16; h += 4) {
        float4 sum = make_float4(0.f, 0.f, 0.f, 0.f);
#pragma unroll
        for (int ss = 0; ss < 8; ss++) {
            float4 a = *(const float4*)&g_acc[ss][base + h];
            sum.x += a.x; sum.y += a.y; sum.z += a.z; sum.w += a.w;
        }
        p += tanhf(sum.x) * pws[hq * 16 + h];
        p += tanhf(sum.y) * pws[hq * 16 + h + 1];
        p += tanhf(sum.z) * pws[hq * 16 + h + 2];
        p += tanhf(sum.w) * pws[hq * 16 + h + 3];
    }
    red[tl][hq] = p;
    __syncthreads();
    if (hq == 0)
        out[bt0 + tl] = pb[0] + red[tl][0] + red[tl][1] + red[tl][2] + red[tl][3];
}

// ---------------------------------------------------------------------------
extern "C" void kernel_launch(void* const* d_in, const int* in_sizes, int n_in,
                              void* d_out, int out_size) {
    const float* x   = (const float*)d_in[0];
    const float* emb = (const float*)d_in[1];
    const float* kw  = (const float*)d_in[2];
    const float* kb  = (const float*)d_in[3];
    const float* qw  = (const float*)d_in[4];
    const float* qb  = (const float*)d_in[5];
    const float* vw  = (const float*)d_in[6];
    const float* pw  = (const float*)d_in[7];
    const float* pb  = (const float*)d_in[8];
    float* out = (float*)d_out;

    cudaFuncSetAttribute(kv_pk,    cudaFuncAttributeMaxDynamicSharedMemorySize, KV_SMEM);
    cudaFuncSetAttribute(denom_pk, cudaFuncAttributeMaxDynamicSharedMemorySize, D_SMEM);
    cudaFuncSetAttribute(out_pk,   cudaFuncAttributeMaxDynamicSharedMemorySize, O_SMEM);

    minmax_kernel<<<1, 1024>>>(x);
    coef_kernel<<<1, 64>>>(qw, qb);
    u_prep<<<(B * T) / 256, 256>>>(x);
    kv_pk<<<(B * S) / 64, 256, KV_SMEM>>>(emb, kw, kb, vw);
    p_prep<<<dim3(S / 128, B), 128>>>();
    denom_pk<<<dim3(S / 64, 4, B), 256, D_SMEM>>>();
    rd_prep<<<(B * S) / 256, 256>>>();
    out_pk<<<dim3(T / 128, 8, B), 256, O_SMEM>>>();
    final_ep<<<(B * T) / 64, 256>>>(pw, pb, out);
}

// round 8
// speedup vs baseline: 1.0571x; 1.0571x over previous
#include <cuda_runtime.h>
#include <math.h>
#include <stdint.h>

#define B 4
#define T 4096
#define S 4096
#define E 512
#define H 64
#define RR 16
#define QSCALE 0.18033688011112042

typedef unsigned long long u64;

// ------------------ device scratch ------------------
__device__ float g_c, g_r;
__device__ float g_V[RR * 64];
__device__ float g_ut[B * RR * T];
__device__ float g_k[B * S * H];
__device__ float g_v[B * S * H];
__device__ float g_P[B * RR * S];
__device__ float g_d4[4][B * S];
__device__ float g_rd[B * S];
__device__ float g_acc[8][B * T * H];

// ------------------ helpers ------------------
__device__ __forceinline__ void ffma2(u64& d, u64 a, u64 b) {
    asm("fma.rn.f32x2 %0, %1, %2, %0;" : "+l"(d) : "l"(a), "l"(b));
}
__device__ __forceinline__ u64 pk2(float x, float y) {
    u64 r; asm("mov.b64 %0, {%1,%2};" : "=l"(r) : "f"(x), "f"(y)); return r;
}
__device__ __forceinline__ float2 up2(u64 v) {
    float2 r; asm("mov.b64 {%0,%1}, %2;" : "=f"(r.x), "=f"(r.y) : "l"(v)); return r;
}
__device__ __forceinline__ float ex2f(float x) {
    float y; asm("ex2.approx.ftz.f32 %0, %1;" : "=f"(y) : "f"(x)); return y;
}

// ------------------ tiny prep ------------------
__global__ __launch_bounds__(1024) void minmax_kernel(const float* __restrict__ x) {
    __shared__ float smn[1024], smx[1024];
    int tid = threadIdx.x;
    float mn = 1e30f, mx = -1e30f;
    for (int i = tid; i < B * T; i += 1024) {
        float v = x[i]; mn = fminf(mn, v); mx = fmaxf(mx, v);
    }
    smn[tid] = mn; smx[tid] = mx; __syncthreads();
    for (int o = 512; o > 0; o >>= 1) {
        if (tid < o) { smn[tid] = fminf(smn[tid], smn[tid+o]); smx[tid] = fmaxf(smx[tid], smx[tid+o]); }
        __syncthreads();
    }
    if (tid == 0) { g_c = 0.5f*(smn[0]+smx[0]); g_r = 0.5f*(smx[0]-smn[0]) + 1e-6f; }
}

__global__ void coef_kernel(const float* __restrict__ qw, const float* __restrict__ qb) {
    int h = threadIdx.x;
    double c = (double)g_c, r = (double)g_r;
    double f[RR];
    for (int j = 0; j < RR; j++) {
        double th = 3.14159265358979323846 * (j + 0.5) / RR;
        f[j] = QSCALE * tanh((double)qw[h] * (c + r*cos(th)) + (double)qb[h]);
    }
    for (int m = 0; m < RR; m++) {
        double a = 0.0;
        for (int j = 0; j < RR; j++) a += f[j] * cos(3.14159265358979323846 * m * (j+0.5) / RR);
        a *= (m == 0 ? 1.0 : 2.0) / RR;
        g_V[m * 64 + h] = (float)a;
    }
}

__global__ __launch_bounds__(256) void u_prep(const float* __restrict__ x) {
    int i = blockIdx.x * 256 + threadIdx.x;
    int b = i >> 12, t = i & 4095;
    float u = (x[i] - g_c) / g_r;
    float tm2 = 1.0f, tm1 = u;
    g_ut[(b*RR+0)*T + t] = 1.0f;
    g_ut[(b*RR+1)*T + t] = u;
#pragma unroll
    for (int m = 2; m < RR; m++) {
        float tc = 2.0f*u*tm1 - tm2;
        g_ut[(b*RR+m)*T + t] = tc;
        tm2 = tm1; tm1 = tc;
    }
}

// ======================= kv kernel =======================
// 64 rows x 128 cols. warp wr: rows 8wr..8wr+7; lane l: cols 4l..4l+3 (2 col-pairs).
// a = dup(emb row value) [bcast], b = col-pair u64 [lane, 16B stride, conflict-free].
#define KV_EA 0                 // [64 e][66] u64: dup emb, idx e*66 + r
#define KV_WP (64 * 66)         // [64 e][66] u64: col-pairs, idx e*66 + cp
#define KV_U64 (2 * 64 * 66)
#define KV_SMEM (KV_U64 * 8)

__global__ __launch_bounds__(256, 2) void kv_pk(const float* __restrict__ emb,
                                                const float* __restrict__ kw,
                                                const float* __restrict__ kb,
                                                const float* __restrict__ vw) {
    extern __shared__ __align__(16) u64 sm8[];
    const int r0 = blockIdx.x * 64;
    const int tid = threadIdx.x;
    const int wr = tid >> 5, l = tid & 31;

    u64 acc[8][2] = {};

    for (int e0 = 0; e0 < E; e0 += 64) {
        __syncthreads();
        // stage A: dup emb values. lane-consecutive r -> STS.64 stride 1 u64 (CF)
#pragma unroll
        for (int k = 0; k < 4; k++) {
            int idx = k * 256 + tid;
            int r = idx & 63, eg = (idx >> 6) << 2;
            float4 v = *(const float4*)(emb + (size_t)(r0 + r) * E + e0 + eg);
            sm8[KV_EA + (eg+0)*66 + r] = pk2(v.x, v.x);
            sm8[KV_EA + (eg+1)*66 + r] = pk2(v.y, v.y);
            sm8[KV_EA + (eg+2)*66 + r] = pk2(v.z, v.z);
            sm8[KV_EA + (eg+3)*66 + r] = pk2(v.w, v.w);
        }
        // stage B: col-pairs. lane-consecutive cp -> CF
#pragma unroll
        for (int k = 0; k < 4; k++) {
            int idx = k * 256 + tid;
            int cp = idx & 63, eg = (idx >> 6) << 2;
            const float* w0p;
            const float* w1p;
            if (cp < 32) { w0p = kw + (size_t)(2*cp) * E; w1p = kw + (size_t)(2*cp+1) * E; }
            else         { w0p = vw + (size_t)(2*cp-64) * E; w1p = vw + (size_t)(2*cp-63) * E; }
            float4 a = *(const float4*)(w0p + e0 + eg);
            float4 bq = *(const float4*)(w1p + e0 + eg);
            sm8[KV_WP + (eg+0)*66 + cp] = pk2(a.x, bq.x);
            sm8[KV_WP + (eg+1)*66 + cp] = pk2(a.y, bq.y);
            sm8[KV_WP + (eg+2)*66 + cp] = pk2(a.z, bq.z);
            sm8[KV_WP + (eg+3)*66 + cp] = pk2(a.w, bq.w);
        }
        __syncthreads();
#pragma unroll 8
        for (int e = 0; e < 64; e++) {
            const u64* ap = sm8 + KV_EA + e*66 + 8*wr;
            ulonglong2 a01 = *(const ulonglong2*)(ap + 0);
            ulonglong2 a23 = *(const ulonglong2*)(ap + 2);
            ulonglong2 a45 = *(const ulonglong2*)(ap + 4);
            ulonglong2 a67 = *(const ulonglong2*)(ap + 6);
            u64 ar[8] = {a01.x, a01.y, a23.x, a23.y, a45.x, a45.y, a67.x, a67.y};
            ulonglong2 bb = *(const ulonglong2*)(sm8 + KV_WP + e*66 + 2*l);
#pragma unroll
            for (int j = 0; j < 8; j++) {
                ffma2(acc[j][0], ar[j], bb.x);
                ffma2(acc[j][1], ar[j], bb.y);
            }
        }
    }
    // epilogue: row 8wr+j, cols 4l..4l+3 (full sums; halves are col pairs)
    float4 bias = make_float4(0.f, 0.f, 0.f, 0.f);
    if (l < 16) bias = *(const float4*)(kb + 4*l);
#pragma unroll
    for (int j = 0; j < 8; j++) {
        float2 c01 = up2(acc[j][0]);
        float2 c23 = up2(acc[j][1]);
        size_t row = (size_t)r0 + 8*wr + j;
        float4 o;
        if (l < 16) {
            o.x = tanhf(c01.x + bias.x); o.y = tanhf(c01.y + bias.y);
            o.z = tanhf(c23.x + bias.z); o.w = tanhf(c23.y + bias.w);
            *(float4*)(g_k + row * H + 4*l) = o;
        } else {
            o.x = tanhf(c01.x); o.y = tanhf(c01.y);
            o.z = tanhf(c23.x); o.w = tanhf(c23.y);
            *(float4*)(g_v + row * H + 4*l - 64) = o;
        }
    }
}

// ------------------ P[b][m][s] = sum_h V[m][h] k[b][s][h] ------------------
__global__ __launch_bounds__(128) void p_prep() {
    __shared__ float Vs[RR * 64];
    __shared__ float ks[128][68];
    const int b = blockIdx.y, s0 = blockIdx.x * 128, tid = threadIdx.x;
    for (int i = tid; i < RR * 64; i += 128) Vs[i] = g_V[i];
    for (int i = tid; i < 128 * 16; i += 128) {
        int s = i >> 4, h4 = (i & 15) * 4;
        *(float4*)&ks[s][h4] = *(const float4*)(g_k + ((size_t)(b*S + s0 + s)) * H + h4);
    }
    __syncthreads();
    float kr[64];
#pragma unroll
    for (int h = 0; h < 64; h++) kr[h] = ks[tid][h];
#pragma unroll
    for (int m = 0; m < RR; m++) {
        float a = 0.0f;
#pragma unroll
        for (int h = 0; h < 64; h++) a += Vs[m * 64 + h] * kr[h];
        g_P[(b*RR + m) * S + s0 + tid] = a;
    }
}

// ======================= denom kernel (unchanged from R7 — conflict-free) ===
#define D_UT 0
#define D_PD 8256
#define D_U64 9312
#define D_SMEM (9312 * 8 + 256)

__global__ __launch_bounds__(256, 2) void denom_pk() {
    extern __shared__ __align__(16) u64 sm8[];
    float* dsh = (float*)(sm8 + D_U64);
    const int b = blockIdx.z, tq = blockIdx.y, sb = blockIdx.x * 64;
    const int t0 = tq * 1024;
    const int tid = threadIdx.x;
    const int wr = tid >> 5, l = tid & 31;

#pragma unroll
    for (int k = 0; k < 32; k++) {
        int idx = tid + k * 256;
        int m = idx >> 9, tp = idx & 511;
        sm8[D_UT + m*516 + tp] = ((const u64*)(g_ut + (size_t)(b*RR + m)*T + t0))[tp];
    }
#pragma unroll
    for (int k = 0; k < 4; k++) {
        int idx = tid + k * 256;
        int m = idx >> 6, s = idx & 63;
        float p = g_P[(b*RR + m)*S + sb + s];
        sm8[D_PD + m*66 + s] = pk2(p, p);
    }
    if (tid < 64) dsh[tid] = 0.0f;
    __syncthreads();

    float ds0 = 0.0f, ds1 = 0.0f;
    for (int it = 0; it < 8; it++) {
        const int tpb = 64*wr + 8*it;
        u64 lac[8][2] = {};
#pragma unroll
        for (int m = 0; m < RR; m++) {
            const u64* ap = sm8 + D_UT + m*516 + tpb;
            ulonglong2 a01 = *(const ulonglong2*)(ap + 0);
            ulonglong2 a23 = *(const ulonglong2*)(ap + 2);
            ulonglong2 a45 = *(const ulonglong2*)(ap + 4);
            ulonglong2 a67 = *(const ulonglong2*)(ap + 6);
            u64 ar[8] = {a01.x, a01.y, a23.x, a23.y, a45.x, a45.y, a67.x, a67.y};
            ulonglong2 bb = *(const ulonglong2*)(sm8 + D_PD + m*66 + 2*l);
#pragma unroll
            for (int j = 0; j < 8; j++) {
                ffma2(lac[j][0], ar[j], bb.x);
                ffma2(lac[j][1], ar[j], bb.y);
            }
        }
#pragma unroll
        for (int j = 0; j < 8; j++) {
            float2 f0 = up2(lac[j][0]);
            float2 f1 = up2(lac[j][1]);
            ds0 += ex2f(f0.x) + ex2f(f0.y);
            ds1 += ex2f(f1.x) + ex2f(f1.y);
        }
    }
    atomicAdd(&dsh[2*l], ds0);
    atomicAdd(&dsh[2*l+1], ds1);
    __syncthreads();
    if (tid < 64) g_d4[tq][b*S + sb + tid] = dsh[tid];
}

__global__ __launch_bounds__(256) void rd_prep() {
    int i = blockIdx.x * 256 + threadIdx.x;
    g_rd[i] = 1.0f / (g_d4[0][i] + g_d4[1][i] + g_d4[2][i] + g_d4[3][i]);
}

// ======================= out kernel =======================
// CTA: 64 t x 512 s. warp wr: t = 8wr..8wr+7. lane l: h = 2l, 2l+1.
// stage1: L via U t-pairs (bcast) x P dup (lane, 16B CF); W stored as s-pair u64
//         at [t*34 + l] (8B stride, CF). warp-private -> __syncwarp.
// stage2: a = W s-pair u64 (bcast), b = v s-pair u64 (lane 16B CF);
//         acc halves = even/odd-s partial sums.
#define O_UT 0                   // [16 m][34] u64 t-pairs (32 + pad)
#define O_PD 544                 // [16 m][66] u64 P dup
#define O_W2 1600                // [64 t][34] u64 s-pairs (32 + pad)
#define O_VD 3776                // [32 sp][66] u64 v s-pairs over h
#define O_RD 5888                // 64 floats
#define O_U64 5920
#define O_SMEM (O_U64 * 8)

__global__ __launch_bounds__(256, 2) void out_pk() {
    extern __shared__ __align__(16) u64 sm8[];
    float* rds = (float*)(sm8 + O_RD);
    const int b = blockIdx.z, ss = blockIdx.y, tb0 = blockIdx.x * 64;
    const int tid = threadIdx.x;
    const int wr = tid >> 5, l = tid & 31;

    // UT staging: lane-consecutive tp -> CF
#pragma unroll
    for (int k = 0; k < 2; k++) {
        int idx = k * 256 + tid;
        int m = idx >> 5, tp = idx & 31;
        sm8[O_UT + m*34 + tp] = ((const u64*)(g_ut + (size_t)(b*RR + m)*T + tb0))[tp];
    }

    u64 oacc[8][2] = {};

    for (int st = 0; st < 8; st++) {
        const int sb = ss * 512 + st * 64;
        __syncthreads();
        // P dup: lane-consecutive s -> CF
#pragma unroll
        for (int k = 0; k < 4; k++) {
            int idx = k * 256 + tid;
            int m = idx >> 6, s = idx & 63;
            float p = g_P[(b*RR + m)*S + sb + s];
            sm8[O_PD + m*66 + s] = pk2(p, p);
        }
        // v s-pairs: lane-consecutive h -> CF; gmem coalesced over h
#pragma unroll
        for (int k = 0; k < 4; k++) {
            int sp = wr + 8*k;
            size_t r0 = (size_t)(b*S + sb + 2*sp) * H;
            float v0 = g_v[r0 + l];
            float v1 = g_v[r0 + H + l];
            sm8[O_VD + sp*66 + l] = pk2(v0, v1);
            float v2 = g_v[r0 + 32 + l];
            float v3 = g_v[r0 + H + 32 + l];
            sm8[O_VD + sp*66 + 32 + l] = pk2(v2, v3);
        }
        if (tid < 64) rds[tid] = g_rd[b*S + sb + tid];
        __syncthreads();

        // ---- stage 1: L[t-pairs 4wr..4wr+3][s = 2l, 2l+1] ----
        u64 lac[4][2] = {};
#pragma unroll
        for (int m = 0; m < RR; m++) {
            const u64* ap = sm8 + O_UT + m*34 + 4*wr;
            ulonglong2 a01 = *(const ulonglong2*)(ap + 0);
            ulonglong2 a23 = *(const ulonglong2*)(ap + 2);
            u64 ar[4] = {a01.x, a01.y, a23.x, a23.y};
            ulonglong2 bb = *(const ulonglong2*)(sm8 + O_PD + m*66 + 2*l);
#pragma unroll
            for (int j = 0; j < 4; j++) {
                ffma2(lac[j][0], ar[j], bb.x);
                ffma2(lac[j][1], ar[j], bb.y);
            }
        }
        {
            float rs0 = rds[2*l], rs1 = rds[2*l+1];
#pragma unroll
            for (int j = 0; j < 4; j++) {
                float2 f0 = up2(lac[j][0]);   // s=2l,   halves (t0, t1)
                float2 f1 = up2(lac[j][1]);   // s=2l+1
                int t0 = 8*wr + 2*j;
                sm8[O_W2 + t0*34 + l]      = pk2(ex2f(f0.x)*rs0, ex2f(f1.x)*rs1);
                sm8[O_W2 + (t0+1)*34 + l]  = pk2(ex2f(f0.y)*rs0, ex2f(f1.y)*rs1);
            }
        }
        __syncwarp();

        // ---- stage 2: acc[t][h] += W[t][s] v[s][h], s-pair packed ----
#pragma unroll 2
        for (int i = 0; i < 16; i++) {
            ulonglong2 vA = *(const ulonglong2*)(sm8 + O_VD + (2*i)*66 + 2*l);
            ulonglong2 vB = *(const ulonglong2*)(sm8 + O_VD + (2*i+1)*66 + 2*l);
#pragma unroll
            for (int tj = 0; tj < 8; tj++) {
                int t = 8*wr + tj;
                ulonglong2 wv = *(const ulonglong2*)(sm8 + O_W2 + t*34 + 2*i);
                ffma2(oacc[tj][0], wv.x, vA.x);
                ffma2(oacc[tj][1], wv.x, vA.y);
                ffma2(oacc[tj][0], wv.y, vB.x);
                ffma2(oacc[tj][1], wv.y, vB.y);
            }
        }
    }

    // writeback: halves = even/odd-s partials
#pragma unroll
    for (int tj = 0; tj < 8; tj++) {
        float2 s0 = up2(oacc[tj][0]);
        float2 s1 = up2(oacc[tj][1]);
        size_t base = ((size_t)(b*T) + tb0 + 8*wr + tj) * H + 2*l;
        *(float2*)&g_acc[ss][base] = make_float2(s0.x + s0.y, s1.x + s1.y);
    }
}

// ------------------ final epilogue ------------------
__global__ __launch_bounds__(256) void final_ep(const float* __restrict__ pw,
                                                const float* __restrict__ pb,
                                                float* __restrict__ out) {
    __shared__ float red[64][5];
    __shared__ float pws[64];
    const int tid = threadIdx.x;
    if (tid < 64) pws[tid] = pw[tid];
    __syncthreads();
    const size_t bt0 = (size_t)blockIdx.x * 64;
    const int tl = tid >> 2, hq = tid & 3;
    const size_t base = (bt0 + tl) * H + hq * 16;
    float p = 0.0f;
#pragma unroll
    for (int h = 0; h < 16; h += 4) {
        float4 sum = make_float4(0.f, 0.f, 0.f, 0.f);
#pragma unroll
        for (int ss = 0; ss < 8; ss++) {
            float4 a = *(const float4*)&g_acc[ss][base + h];
            sum.x += a.x; sum.y += a.y; sum.z += a.z; sum.w += a.w;
        }
        p += tanhf(sum.x) * pws[hq * 16 + h];
        p += tanhf(sum.y) * pws[hq * 16 + h + 1];
        p += tanhf(sum.z) * pws[hq * 16 + h + 2];
        p += tanhf(sum.w) * pws[hq * 16 + h + 3];
    }
    red[tl][hq] = p;
    __syncthreads();
    if (hq == 0)
        out[bt0 + tl] = pb[0] + red[tl][0] + red[tl][1] + red[tl][2] + red[tl][3];
}

// ---------------------------------------------------------------------------
extern "C" void kernel_launch(void* const* d_in, const int* in_sizes, int n_in,
                              void* d_out, int out_size) {
    const float* x   = (const float*)d_in[0];
    const float* emb = (const float*)d_in[1];
    const float* kw  = (const float*)d_in[2];
    const float* kb  = (const float*)d_in[3];
    const float* qw  = (const float*)d_in[4];
    const float* qb  = (const float*)d_in[5];
    const float* vw  = (const float*)d_in[6];
    const float* pw  = (const float*)d_in[7];
    const float* pb  = (const float*)d_in[8];
    float* out = (float*)d_out;

    cudaFuncSetAttribute(kv_pk,    cudaFuncAttributeMaxDynamicSharedMemorySize, KV_SMEM);
    cudaFuncSetAttribute(denom_pk, cudaFuncAttributeMaxDynamicSharedMemorySize, D_SMEM);
    cudaFuncSetAttribute(out_pk,   cudaFuncAttributeMaxDynamicSharedMemorySize, O_SMEM);

    minmax_kernel<<<1, 1024>>>(x);
    coef_kernel<<<1, 64>>>(qw, qb);
    u_prep<<<(B * T) / 256, 256>>>(x);
    kv_pk<<<(B * S) / 64, 256, KV_SMEM>>>(emb, kw, kb, vw);
    p_prep<<<dim3(S / 128, B), 128>>>();
    denom_pk<<<dim3(S / 64, 4, B), 256, D_SMEM>>>();
    rd_prep<<<(B * S) / 256, 256>>>();
    out_pk<<<dim3(T / 64, 8, B), 256, O_SMEM>>>();
    final_ep<<<(B * T) / 64, 256>>>(pw, pb, out);
}

// round 10
// speedup vs baseline: 1.5882x; 1.5024x over previous
#include <cuda_runtime.h>
#include <math.h>
#include <stdint.h>

#define B 4
#define T 4096
#define S 4096
#define E 512
#define H 64
#define RR 16
#define NN 64            // Chebyshev nodes for the t-collapse
#define QSCALE 0.18033688011112042

typedef unsigned long long u64;

// ------------------ device scratch ------------------
__device__ float g_c, g_r;
__device__ float g_V[RR * 64];        // cheb coeffs of q_h(x) (log2-scaled)
__device__ float g_u[B * T];          // normalized x
__device__ float g_k[B * S * H];
__device__ float g_v[B * S * H];
__device__ float g_P[B * RR * S];     // V @ k^T
__device__ float g_G[B * NN * S];     // exp2(L) at nodes (4 MB)
__device__ float g_M[B * NN];         // moments  sum_t T_n(u_t)
__device__ float g_wq[B * NN];        // quadrature weights omega_j
__device__ float g_rd[B * S];         // 1/denom
__device__ float g_F[B * NN];         // out at nodes
__device__ float g_a[B * NN];         // cheb coeffs of F

// ------------------ helpers ------------------
__device__ __forceinline__ void ffma2(u64& d, u64 a, u64 b) {
    asm("fma.rn.f32x2 %0, %1, %2, %0;" : "+l"(d) : "l"(a), "l"(b));
}
__device__ __forceinline__ u64 pk2(float x, float y) {
    u64 r; asm("mov.b64 %0, {%1,%2};" : "=l"(r) : "f"(x), "f"(y)); return r;
}
__device__ __forceinline__ float2 up2(u64 v) {
    float2 r; asm("mov.b64 {%0,%1}, %2;" : "=f"(r.x), "=f"(r.y) : "l"(v)); return r;
}
__device__ __forceinline__ float ex2f(float x) {
    float y; asm("ex2.approx.ftz.f32 %0, %1;" : "=f"(y) : "f"(x)); return y;
}

// ------------------ tiny prep ------------------
__global__ __launch_bounds__(1024) void minmax_kernel(const float* __restrict__ x) {
    __shared__ float smn[1024], smx[1024];
    int tid = threadIdx.x;
    float mn = 1e30f, mx = -1e30f;
    for (int i = tid; i < B * T; i += 1024) {
        float v = x[i]; mn = fminf(mn, v); mx = fmaxf(mx, v);
    }
    smn[tid] = mn; smx[tid] = mx; __syncthreads();
    for (int o = 512; o > 0; o >>= 1) {
        if (tid < o) { smn[tid] = fminf(smn[tid], smn[tid+o]); smx[tid] = fmaxf(smx[tid], smx[tid+o]); }
        __syncthreads();
    }
    if (tid == 0) { g_c = 0.5f*(smn[0]+smx[0]); g_r = 0.5f*(smx[0]-smn[0]) + 1e-6f; }
}

__global__ void coef_kernel(const float* __restrict__ qw, const float* __restrict__ qb) {
    int h = threadIdx.x;
    double c = (double)g_c, r = (double)g_r;
    double f[RR];
    for (int j = 0; j < RR; j++) {
        double th = 3.14159265358979323846 * (j + 0.5) / RR;
        f[j] = QSCALE * tanh((double)qw[h] * (c + r*cos(th)) + (double)qb[h]);
    }
    for (int m = 0; m < RR; m++) {
        double a = 0.0;
        for (int j = 0; j < RR; j++) a += f[j] * cos(3.14159265358979323846 * m * (j+0.5) / RR);
        a *= (m == 0 ? 1.0 : 2.0) / RR;
        g_V[m * 64 + h] = (float)a;
    }
}

__global__ __launch_bounds__(256) void u_prep(const float* __restrict__ x) {
    int i = blockIdx.x * 256 + threadIdx.x;
    g_u[i] = (x[i] - g_c) / g_r;
}

// ======================= kv kernel (R8, validated) =======================
#define KV_EA 0
#define KV_WP (64 * 66)
#define KV_U64 (2 * 64 * 66)
#define KV_SMEM (KV_U64 * 8)

__global__ __launch_bounds__(256, 2) void kv_pk(const float* __restrict__ emb,
                                                const float* __restrict__ kw,
                                                const float* __restrict__ kb,
                                                const float* __restrict__ vw) {
    extern __shared__ __align__(16) u64 sm8[];
    const int r0 = blockIdx.x * 64;
    const int tid = threadIdx.x;
    const int wr = tid >> 5, l = tid & 31;

    u64 acc[8][2] = {};

    for (int e0 = 0; e0 < E; e0 += 64) {
        __syncthreads();
#pragma unroll
        for (int k = 0; k < 4; k++) {
            int idx = k * 256 + tid;
            int r = idx & 63, eg = (idx >> 6) << 2;
            float4 v = *(const float4*)(emb + (size_t)(r0 + r) * E + e0 + eg);
            sm8[KV_EA + (eg+0)*66 + r] = pk2(v.x, v.x);
            sm8[KV_EA + (eg+1)*66 + r] = pk2(v.y, v.y);
            sm8[KV_EA + (eg+2)*66 + r] = pk2(v.z, v.z);
            sm8[KV_EA + (eg+3)*66 + r] = pk2(v.w, v.w);
        }
#pragma unroll
        for (int k = 0; k < 4; k++) {
            int idx = k * 256 + tid;
            int cp = idx & 63, eg = (idx >> 6) << 2;
            const float* w0p;
            const float* w1p;
            if (cp < 32) { w0p = kw + (size_t)(2*cp) * E; w1p = kw + (size_t)(2*cp+1) * E; }
            else         { w0p = vw + (size_t)(2*cp-64) * E; w1p = vw + (size_t)(2*cp-63) * E; }
            float4 a = *(const float4*)(w0p + e0 + eg);
            float4 bq = *(const float4*)(w1p + e0 + eg);
            sm8[KV_WP + (eg+0)*66 + cp] = pk2(a.x, bq.x);
            sm8[KV_WP + (eg+1)*66 + cp] = pk2(a.y, bq.y);
            sm8[KV_WP + (eg+2)*66 + cp] = pk2(a.z, bq.z);
            sm8[KV_WP + (eg+3)*66 + cp] = pk2(a.w, bq.w);
        }
        __syncthreads();
#pragma unroll 8
        for (int e = 0; e < 64; e++) {
            const u64* ap = sm8 + KV_EA + e*66 + 8*wr;
            ulonglong2 a01 = *(const ulonglong2*)(ap + 0);
            ulonglong2 a23 = *(const ulonglong2*)(ap + 2);
            ulonglong2 a45 = *(const ulonglong2*)(ap + 4);
            ulonglong2 a67 = *(const ulonglong2*)(ap + 6);
            u64 ar[8] = {a01.x, a01.y, a23.x, a23.y, a45.x, a45.y, a67.x, a67.y};
            ulonglong2 bb = *(const ulonglong2*)(sm8 + KV_WP + e*66 + 2*l);
#pragma unroll
            for (int j = 0; j < 8; j++) {
                ffma2(acc[j][0], ar[j], bb.x);
                ffma2(acc[j][1], ar[j], bb.y);
            }
        }
    }
    float4 bias = make_float4(0.f, 0.f, 0.f, 0.f);
    if (l < 16) bias = *(const float4*)(kb + 4*l);
#pragma unroll
    for (int j = 0; j < 8; j++) {
        float2 c01 = up2(acc[j][0]);
        float2 c23 = up2(acc[j][1]);
        size_t row = (size_t)r0 + 8*wr + j;
        float4 o;
        if (l < 16) {
            o.x = tanhf(c01.x + bias.x); o.y = tanhf(c01.y + bias.y);
            o.z = tanhf(c23.x + bias.z); o.w = tanhf(c23.y + bias.w);
            *(float4*)(g_k + row * H + 4*l) = o;
        } else {
            o.x = tanhf(c01.x); o.y = tanhf(c01.y);
            o.z = tanhf(c23.x); o.w = tanhf(c23.y);
            *(float4*)(g_v + row * H + 4*l - 64) = o;
        }
    }
}

// ------------------ P[b][m][s] = sum_h V[m][h] k[b][s][h] ------------------
__global__ __launch_bounds__(128) void p_prep() {
    __shared__ float Vs[RR * 64];
    __shared__ float ks[128][68];
    const int b = blockIdx.y, s0 = blockIdx.x * 128, tid = threadIdx.x;
    for (int i = tid; i < RR * 64; i += 128) Vs[i] = g_V[i];
    for (int i = tid; i < 128 * 16; i += 128) {
        int s = i >> 4, h4 = (i & 15) * 4;
        *(float4*)&ks[s][h4] = *(const float4*)(g_k + ((size_t)(b*S + s0 + s)) * H + h4);
    }
    __syncthreads();
    float kr[64];
#pragma unroll
    for (int h = 0; h < 64; h++) kr[h] = ks[tid][h];
#pragma unroll
    for (int m = 0; m < RR; m++) {
        float a = 0.0f;
#pragma unroll
        for (int h = 0; h < 64; h++) a += Vs[m * 64 + h] * kr[h];
        g_P[(b*RR + m) * S + s0 + tid] = a;
    }
}

// ------------- G[b,j,s] = exp2( sum_m T_m(u_j) P[m,s] ) at 64 nodes -------------
__global__ __launch_bounds__(256) void nodeG() {
    __shared__ float Ps[RR][256];
    const int b = blockIdx.z, jq = blockIdx.y, s0 = blockIdx.x * 256, tid = threadIdx.x;
#pragma unroll
    for (int m = 0; m < RR; m++) Ps[m][tid] = g_P[(b*RR + m)*S + s0 + tid];
    __syncthreads();
    float pv[RR];
#pragma unroll
    for (int m = 0; m < RR; m++) pv[m] = Ps[m][tid];
    for (int jl = 0; jl < 16; jl++) {
        int j = jq * 16 + jl;
        float uj = cospif((j + 0.5f) / (float)NN);
        float t0 = 1.0f, t1 = uj;
        float L = pv[0] + uj * pv[1];
#pragma unroll
        for (int m = 2; m < RR; m++) {
            float t2 = 2.0f*uj*t1 - t0;
            L += t2 * pv[m];
            t0 = t1; t1 = t2;
        }
        g_G[((size_t)(b*NN + j))*S + s0 + tid] = ex2f(L);
    }
}

// ------------- moments M[b,n] = sum_t T_n(u_t), deterministic reduce -------------
__global__ __launch_bounds__(128) void moments_k() {
    __shared__ float sMp[NN][4];
    const int b = blockIdx.x, tid = threadIdx.x;
    const int wr = tid >> 5;
    float acc[NN];
#pragma unroll
    for (int n = 0; n < NN; n++) acc[n] = 0.0f;
    for (int t = tid; t < T; t += 128) {
        float u = g_u[b*T + t];
        float t0 = 1.0f, t1 = u;
        acc[0] += 1.0f; acc[1] += u;
#pragma unroll
        for (int n = 2; n < NN; n++) {
            float t2 = 2.0f*u*t1 - t0;
            acc[n] += t2;
            t0 = t1; t1 = t2;
        }
    }
#pragma unroll
    for (int n = 0; n < NN; n++) {
        float v = acc[n];
        v += __shfl_xor_sync(0xffffffff, v, 16);
        v += __shfl_xor_sync(0xffffffff, v, 8);
        v += __shfl_xor_sync(0xffffffff, v, 4);
        v += __shfl_xor_sync(0xffffffff, v, 2);
        v += __shfl_xor_sync(0xffffffff, v, 1);
        if ((tid & 31) == 0) sMp[n][wr] = v;
    }
    __syncthreads();
    if (tid < NN) g_M[b*NN + tid] = sMp[tid][0] + sMp[tid][1] + sMp[tid][2] + sMp[tid][3];
}

// ------------- omega[b,j] = sum_n fac_n T_n(u_j) M[b,n] -------------
__global__ void weights_k() {
    int tid = threadIdx.x;              // 256 = B*NN
    int b = tid >> 6, j = tid & 63;
    float uj = cospif((j + 0.5f) / (float)NN);
    float t0 = 1.0f, t1 = uj;
    float w = g_M[b*NN + 0] * (1.0f/NN) + g_M[b*NN + 1] * t1 * (2.0f/NN);
    for (int n = 2; n < NN; n++) {
        float t2 = 2.0f*uj*t1 - t0;
        w += g_M[b*NN + n] * t2 * (2.0f/NN);
        t0 = t1; t1 = t2;
    }
    g_wq[tid] = w;
}

// ------------- rd[b,s] = 1 / sum_j omega_j G[b,j,s] -------------
__global__ __launch_bounds__(256) void rdenom_k() {
    __shared__ float ws[NN];
    const int b = blockIdx.y, s = blockIdx.x * 256 + threadIdx.x;
    if (threadIdx.x < NN) ws[threadIdx.x] = g_wq[b*NN + threadIdx.x];
    __syncthreads();
    float d = 0.0f;
#pragma unroll 8
    for (int j = 0; j < NN; j++) d += ws[j] * g_G[((size_t)(b*NN + j))*S + s];
    g_rd[b*S + s] = 1.0f / d;
}

// ------------- F[b,j] = pb + sum_h pw[h] tanh( sum_s G rd v ) -------------
#define NO_V 0                   // [128 s][34] u64 (32 h-pairs + pad)
#define NO_W 4352                // [8 j][130] u64 dup W
#define NO_U64 (4352 + 8*130)
#define NO_SMEM (NO_U64 * 8)

__global__ __launch_bounds__(256) void node_out(const float* __restrict__ pw,
                                                const float* __restrict__ pb) {
    extern __shared__ __align__(16) u64 smno[];
    const int b = blockIdx.y, jg = blockIdx.x;
    const int tid = threadIdx.x, wr = tid >> 5, l = tid & 31;

    u64 acc = 0;
    for (int s0 = 0; s0 < S; s0 += 128) {
        __syncthreads();
#pragma unroll
        for (int k = 0; k < 16; k++) {
            int idx = k * 256 + tid;      // 128 s x 32 hp
            int s = idx >> 5, hp = idx & 31;
            float2 vv = *(const float2*)(g_v + (size_t)(b*S + s0 + s)*H + 2*hp);
            smno[NO_V + s*34 + hp] = pk2(vv.x, vv.y);
        }
#pragma unroll
        for (int k = 0; k < 4; k++) {
            int idx = k * 256 + tid;      // 8 j x 128 s
            int jl = idx >> 7, sl = idx & 127;
            float wv = g_G[((size_t)(b*NN + jg*8 + jl))*S + s0 + sl] * g_rd[b*S + s0 + sl];
            smno[NO_W + jl*130 + sl] = pk2(wv, wv);
        }
        __syncthreads();
#pragma unroll 8
        for (int s = 0; s < 128; s++) {
            u64 wv = smno[NO_W + wr*130 + s];
            u64 vv = smno[NO_V + s*34 + l];
            ffma2(acc, wv, vv);
        }
    }
    float2 o = up2(acc);
    float part = tanhf(o.x)*pw[2*l] + tanhf(o.y)*pw[2*l+1];
#pragma unroll
    for (int d = 16; d; d >>= 1) part += __shfl_xor_sync(0xffffffff, part, d);
    if (l == 0) g_F[b*NN + jg*8 + wr] = pb[0] + part;
}

// ------------- a[b,n] = fac_n sum_j F[b,j] T_n(u_j) -------------
__global__ void chebfit_k() {
    int tid = threadIdx.x;              // 256 = B*NN
    int b = tid >> 6, n = tid & 63;
    float a = 0.0f;
    for (int j = 0; j < NN; j++) {
        float tn = cospif((float)(n * (2*j + 1)) / (2.0f * NN));
        a += g_F[b*NN + j] * tn;
    }
    g_a[tid] = a * ((n == 0 ? 1.0f : 2.0f) / NN);
}

// ------------- out[b,t] = Clenshaw(a[b,:], u_t) -------------
__global__ __launch_bounds__(256) void final_eval(float* __restrict__ out) {
    __shared__ float as[B * NN];
    int tid = threadIdx.x;
    as[tid] = g_a[tid];
    __syncthreads();
    int i = blockIdx.x * 256 + tid;
    int b = i >> 12;
    float u = g_u[i];
    const float* a = &as[b * NN];
    float u2 = 2.0f * u;
    float bk1 = 0.0f, bk2 = 0.0f;
#pragma unroll
    for (int n = NN - 1; n >= 1; n--) {
        float bk = a[n] + u2*bk1 - bk2;
        bk2 = bk1; bk1 = bk;
    }
    out[i] = a[0] + u*bk1 - bk2;
}

// ---------------------------------------------------------------------------
extern "C" void kernel_launch(void* const* d_in, const int* in_sizes, int n_in,
                              void* d_out, int out_size) {
    const float* x   = (const float*)d_in[0];
    const float* emb = (const float*)d_in[1];
    const float* kw  = (const float*)d_in[2];
    const float* kb  = (const float*)d_in[3];
    const float* qw  = (const float*)d_in[4];
    const float* qb  = (const float*)d_in[5];
    const float* vw  = (const float*)d_in[6];
    const float* pw  = (const float*)d_in[7];
    const float* pb  = (const float*)d_in[8];
    float* out = (float*)d_out;

    cudaFuncSetAttribute(kv_pk,    cudaFuncAttributeMaxDynamicSharedMemorySize, KV_SMEM);
    cudaFuncSetAttribute(node_out, cudaFuncAttributeMaxDynamicSharedMemorySize, NO_SMEM);

    minmax_kernel<<<1, 1024>>>(x);
    coef_kernel<<<1, 64>>>(qw, qb);
    u_prep<<<(B * T) / 256, 256>>>(x);
    kv_pk<<<(B * S) / 64, 256, KV_SMEM>>>(emb, kw, kb, vw);
    p_prep<<<dim3(S / 128, B), 128>>>();
    nodeG<<<dim3(S / 256, 4, B), 256>>>();
    moments_k<<<B, 128>>>();
    weights_k<<<1, 256>>>();
    rdenom_k<<<dim3(S / 256, B), 256>>>();
    node_out<<<dim3(8, B), 256, NO_SMEM>>>(pw, pb);
    chebfit_k<<<1, 256>>>();
    final_eval<<<(B * T) / 256, 256>>>(out);
}

// round 11
// speedup vs baseline: 2.5214x; 1.5876x over previous
#include <cuda_runtime.h>
#include <math.h>
#include <stdint.h>

#define B 4
#define T 4096
#define S 4096
#define E 512
#define H 64
#define RR 16
#define NN 64
#define QSCALE 0.18033688011112042
#define PI_D 3.14159265358979323846

typedef unsigned long long u64;

// ------------------ device scratch ------------------
__device__ float g_V[RR * 64];
__device__ float g_u[B * T];
__device__ float g_k[B * S * H];
__device__ float g_v[B * S * H];
__device__ float g_P[B * RR * S];
__device__ float g_G[B * NN * S];
__device__ float g_wq[B * NN];
__device__ float g_rd[B * S];
__device__ float g_op[8 * B * NN * H];   // node-out partials per s-split
__device__ float g_a[B * NN];

// ------------------ helpers ------------------
__device__ __forceinline__ void ffma2(u64& d, u64 a, u64 b) {
    asm("fma.rn.f32x2 %0, %1, %2, %0;" : "+l"(d) : "l"(a), "l"(b));
}
__device__ __forceinline__ u64 pk2(float x, float y) {
    u64 r; asm("mov.b64 %0, {%1,%2};" : "=l"(r) : "f"(x), "f"(y)); return r;
}
__device__ __forceinline__ float2 up2(u64 v) {
    float2 r; asm("mov.b64 {%0,%1}, %2;" : "=f"(r.x), "=f"(r.y) : "l"(v)); return r;
}
__device__ __forceinline__ float ex2f(float x) {
    float y; asm("ex2.approx.ftz.f32 %0, %1;" : "=f"(y) : "f"(x)); return y;
}

// =============== prep: minmax + cheb coeffs of q + u ===============
__global__ __launch_bounds__(1024) void prep_k(const float* __restrict__ x,
                                               const float* __restrict__ qw,
                                               const float* __restrict__ qb) {
    __shared__ float smn[1024], smx[1024];
    __shared__ double fd[64][17];
    __shared__ float cc[2];
    const int tid = threadIdx.x;
    float mn = 1e30f, mx = -1e30f;
    for (int i = tid; i < B * T; i += 1024) {
        float v = x[i]; mn = fminf(mn, v); mx = fmaxf(mx, v);
    }
    smn[tid] = mn; smx[tid] = mx; __syncthreads();
    for (int o = 512; o > 0; o >>= 1) {
        if (tid < o) { smn[tid] = fminf(smn[tid], smn[tid+o]); smx[tid] = fmaxf(smx[tid], smx[tid+o]); }
        __syncthreads();
    }
    if (tid == 0) {
        cc[0] = 0.5f * (smn[0] + smx[0]);
        cc[1] = 0.5f * (smx[0] - smn[0]) + 1e-6f;
    }
    __syncthreads();
    const float c = cc[0], r = cc[1];
    {   // node values of q_h (1 double tanh per thread)
        int h = tid >> 4, j = tid & 15;
        double th = PI_D * (j + 0.5) / RR;
        fd[h][j] = QSCALE * tanh((double)qw[h] * ((double)c + (double)r * cos(th)) + (double)qb[h]);
    }
    __syncthreads();
    {   // DCT -> coefficients
        int h = tid >> 4, m = tid & 15;
        double a = 0.0;
        for (int j = 0; j < RR; j++) a += fd[h][j] * cos(PI_D * m * (j + 0.5) / RR);
        a *= (m == 0 ? 1.0 : 2.0) / RR;
        g_V[m * 64 + h] = (float)a;
    }
    for (int i = tid; i < B * T; i += 1024) g_u[i] = (x[i] - c) / r;
}

// =============== moments + quadrature weights (per batch) ===============
__global__ __launch_bounds__(512) void momw_k() {
    __shared__ float sM[NN][17];
    __shared__ float sMM[NN];
    const int b = blockIdx.x, tid = threadIdx.x;
    const int wr = tid >> 5, l = tid & 31;
    float acc[NN];
#pragma unroll
    for (int n = 0; n < NN; n++) acc[n] = 0.0f;
    for (int t = tid; t < T; t += 512) {
        float u = g_u[b*T + t];
        float t0 = 1.0f, t1 = u;
        acc[0] += 1.0f; acc[1] += u;
#pragma unroll
        for (int n = 2; n < NN; n++) {
            float t2 = 2.0f*u*t1 - t0;
            acc[n] += t2;
            t0 = t1; t1 = t2;
        }
    }
#pragma unroll
    for (int n = 0; n < NN; n++) {
        float v = acc[n];
        v += __shfl_xor_sync(0xffffffff, v, 16);
        v += __shfl_xor_sync(0xffffffff, v, 8);
        v += __shfl_xor_sync(0xffffffff, v, 4);
        v += __shfl_xor_sync(0xffffffff, v, 2);
        v += __shfl_xor_sync(0xffffffff, v, 1);
        if (l == 0) sM[n][wr] = v;
    }
    __syncthreads();
    if (tid < NN) {
        float s = 0.0f;
#pragma unroll
        for (int w = 0; w < 16; w++) s += sM[tid][w];
        sMM[tid] = s;
    }
    __syncthreads();
    if (tid < NN) {
        int j = tid;
        float uj = cospif((j + 0.5f) / (float)NN);
        float t0 = 1.0f, t1 = uj;
        float w = sMM[0] * (1.0f/NN) + sMM[1] * t1 * (2.0f/NN);
        for (int n = 2; n < NN; n++) {
            float t2 = 2.0f*uj*t1 - t0;
            w += sMM[n] * t2 * (2.0f/NN);
            t0 = t1; t1 = t2;
        }
        g_wq[b*NN + j] = w;
    }
}

// =============== kv kernel (R8 layout + ping-pong pipeline) ===============
#define KV_EA 0
#define KV_WP (64 * 66)
#define KV_U64 (2 * 64 * 66)
#define KV_SMEM (KV_U64 * 8)

__global__ __launch_bounds__(256, 2) void kv_pk(const float* __restrict__ emb,
                                                const float* __restrict__ kw,
                                                const float* __restrict__ kb,
                                                const float* __restrict__ vw) {
    extern __shared__ __align__(16) u64 sm8[];
    const int r0 = blockIdx.x * 64;
    const int tid = threadIdx.x;
    const int wr = tid >> 5, l = tid & 31;

    u64 acc[8][2] = {};

    for (int e0 = 0; e0 < E; e0 += 64) {
        __syncthreads();
#pragma unroll
        for (int k = 0; k < 4; k++) {
            int idx = k * 256 + tid;
            int r = idx & 63, eg = (idx >> 6) << 2;
            float4 v = *(const float4*)(emb + (size_t)(r0 + r) * E + e0 + eg);
            sm8[KV_EA + (eg+0)*66 + r] = pk2(v.x, v.x);
            sm8[KV_EA + (eg+1)*66 + r] = pk2(v.y, v.y);
            sm8[KV_EA + (eg+2)*66 + r] = pk2(v.z, v.z);
            sm8[KV_EA + (eg+3)*66 + r] = pk2(v.w, v.w);
        }
#pragma unroll
        for (int k = 0; k < 4; k++) {
            int idx = k * 256 + tid;
            int cp = idx & 63, eg = (idx >> 6) << 2;
            const float* w0p;
            const float* w1p;
            if (cp < 32) { w0p = kw + (size_t)(2*cp) * E; w1p = kw + (size_t)(2*cp+1) * E; }
            else         { w0p = vw + (size_t)(2*cp-64) * E; w1p = vw + (size_t)(2*cp-63) * E; }
            float4 a = *(const float4*)(w0p + e0 + eg);
            float4 bq = *(const float4*)(w1p + e0 + eg);
            sm8[KV_WP + (eg+0)*66 + cp] = pk2(a.x, bq.x);
            sm8[KV_WP + (eg+1)*66 + cp] = pk2(a.y, bq.y);
            sm8[KV_WP + (eg+2)*66 + cp] = pk2(a.z, bq.z);
            sm8[KV_WP + (eg+3)*66 + cp] = pk2(a.w, bq.w);
        }
        __syncthreads();

        // ping-pong pipelined inner loop
        ulonglong2 A01[2], A23[2], A45[2], A67[2], BB[2];
        {
            const u64* ap = sm8 + KV_EA + 8*wr;
            A01[0] = *(const ulonglong2*)(ap + 0);
            A23[0] = *(const ulonglong2*)(ap + 2);
            A45[0] = *(const ulonglong2*)(ap + 4);
            A67[0] = *(const ulonglong2*)(ap + 6);
            BB[0]  = *(const ulonglong2*)(sm8 + KV_WP + 2*l);
        }
#pragma unroll
        for (int e = 0; e < 64; e += 2) {
            {   // prefetch e+1 into buffer 1
                const u64* ap = sm8 + KV_EA + (e+1)*66 + 8*wr;
                A01[1] = *(const ulonglong2*)(ap + 0);
                A23[1] = *(const ulonglong2*)(ap + 2);
                A45[1] = *(const ulonglong2*)(ap + 4);
                A67[1] = *(const ulonglong2*)(ap + 6);
                BB[1]  = *(const ulonglong2*)(sm8 + KV_WP + (e+1)*66 + 2*l);
            }
            {   // compute e (buffer 0)
                u64 ar[8] = {A01[0].x, A01[0].y, A23[0].x, A23[0].y,
                             A45[0].x, A45[0].y, A67[0].x, A67[0].y};
#pragma unroll
                for (int j = 0; j < 8; j++) {
                    ffma2(acc[j][0], ar[j], BB[0].x);
                    ffma2(acc[j][1], ar[j], BB[0].y);
                }
            }
            if (e + 2 < 64) {   // prefetch e+2 into buffer 0
                const u64* ap = sm8 + KV_EA + (e+2)*66 + 8*wr;
                A01[0] = *(const ulonglong2*)(ap + 0);
                A23[0] = *(const ulonglong2*)(ap + 2);
                A45[0] = *(const ulonglong2*)(ap + 4);
                A67[0] = *(const ulonglong2*)(ap + 6);
                BB[0]  = *(const ulonglong2*)(sm8 + KV_WP + (e+2)*66 + 2*l);
            }
            {   // compute e+1 (buffer 1)
                u64 ar[8] = {A01[1].x, A01[1].y, A23[1].x, A23[1].y,
                             A45[1].x, A45[1].y, A67[1].x, A67[1].y};
#pragma unroll
                for (int j = 0; j < 8; j++) {
                    ffma2(acc[j][0], ar[j], BB[1].x);
                    ffma2(acc[j][1], ar[j], BB[1].y);
                }
            }
        }
    }
    float4 bias = make_float4(0.f, 0.f, 0.f, 0.f);
    if (l < 16) bias = *(const float4*)(kb + 4*l);
#pragma unroll
    for (int j = 0; j < 8; j++) {
        float2 c01 = up2(acc[j][0]);
        float2 c23 = up2(acc[j][1]);
        size_t row = (size_t)r0 + 8*wr + j;
        float4 o;
        if (l < 16) {
            o.x = tanhf(c01.x + bias.x); o.y = tanhf(c01.y + bias.y);
            o.z = tanhf(c23.x + bias.z); o.w = tanhf(c23.y + bias.w);
            *(float4*)(g_k + row * H + 4*l) = o;
        } else {
            o.x = tanhf(c01.x); o.y = tanhf(c01.y);
            o.z = tanhf(c23.x); o.w = tanhf(c23.y);
            *(float4*)(g_v + row * H + 4*l - 64) = o;
        }
    }
}

// =============== P[b][m][s] = sum_h V[m][h] k[b][s][h] ===============
__global__ __launch_bounds__(128) void p_prep() {
    __shared__ float Vs[RR * 64];
    __shared__ float ks[128][68];
    const int b = blockIdx.y, s0 = blockIdx.x * 128, tid = threadIdx.x;
    for (int i = tid; i < RR * 64; i += 128) Vs[i] = g_V[i];
    for (int i = tid; i < 128 * 16; i += 128) {
        int s = i >> 4, h4 = (i & 15) * 4;
        *(float4*)&ks[s][h4] = *(const float4*)(g_k + ((size_t)(b*S + s0 + s)) * H + h4);
    }
    __syncthreads();
    float kr[64];
#pragma unroll
    for (int h = 0; h < 64; h++) kr[h] = ks[tid][h];
#pragma unroll
    for (int m = 0; m < RR; m++) {
        float a = 0.0f;
#pragma unroll
        for (int h = 0; h < 64; h++) a += Vs[m * 64 + h] * kr[h];
        g_P[(b*RR + m) * S + s0 + tid] = a;
    }
}

// =============== fused: G at all 64 nodes + reciprocal denom ===============
__global__ __launch_bounds__(256) void gGrd_k() {
    __shared__ float Ps[RR][257];
    __shared__ float ws[NN];
    const int b = blockIdx.y, s0 = blockIdx.x * 256, tid = threadIdx.x;
#pragma unroll
    for (int m = 0; m < RR; m++) Ps[m][tid] = g_P[(b*RR + m)*S + s0 + tid];
    if (tid < NN) ws[tid] = g_wq[b*NN + tid];
    __syncthreads();
    float pv[RR];
#pragma unroll
    for (int m = 0; m < RR; m++) pv[m] = Ps[m][tid];
    float d = 0.0f;
    for (int j = 0; j < NN; j++) {
        float uj = cospif((j + 0.5f) / (float)NN);
        float t0 = 1.0f, t1 = uj;
        float L = pv[0] + uj * pv[1];
#pragma unroll
        for (int m = 2; m < RR; m++) {
            float t2 = 2.0f*uj*t1 - t0;
            L += t2 * pv[m];
            t0 = t1; t1 = t2;
        }
        float G = ex2f(L);
        g_G[((size_t)(b*NN + j))*S + s0 + tid] = G;
        d += ws[j] * G;
    }
    g_rd[b*S + s0 + tid] = 1.0f / d;
}

// =============== node out: partial o[b,j,h] per s-split ===============
#define NO_V 0                     // [128 s][34] u64 (32 h-pairs + pad)
#define NO_W 4352                  // [64 j][130] u64 dup W
#define NO_U64 (4352 + 64*130)
#define NO_SMEM (NO_U64 * 8)

__global__ __launch_bounds__(256) void nodeo_k() {
    extern __shared__ __align__(16) u64 smno[];
    const int b = blockIdx.y, sp = blockIdx.x;
    const int tid = threadIdx.x, wr = tid >> 5, l = tid & 31;

    u64 acc8[8] = {};
    for (int sc = 0; sc < 4; sc++) {
        const int s0 = sp*512 + sc*128;
        __syncthreads();
        // v staging with rd folded in: [s][hp]
#pragma unroll
        for (int k = 0; k < 16; k++) {
            int idx = k * 256 + tid;
            int s = idx >> 5, hp = idx & 31;
            float2 vv = *(const float2*)(g_v + (size_t)(b*S + s0 + s)*H + 2*hp);
            float rdv = g_rd[b*S + s0 + s];
            smno[NO_V + s*34 + hp] = pk2(vv.x * rdv, vv.y * rdv);
        }
        // W = G staging, dup: [j][s]
#pragma unroll
        for (int k = 0; k < 32; k++) {
            int idx = k * 256 + tid;
            int j = idx >> 7, sl = idx & 127;
            float wv = g_G[((size_t)(b*NN + j))*S + s0 + sl];
            smno[NO_W + j*130 + sl] = pk2(wv, wv);
        }
        __syncthreads();
#pragma unroll 4
        for (int s = 0; s < 128; s++) {
            u64 vv = smno[NO_V + s*34 + l];
#pragma unroll
            for (int jj = 0; jj < 8; jj++)
                ffma2(acc8[jj], smno[NO_W + (wr + 8*jj)*130 + s], vv);
        }
    }
#pragma unroll
    for (int jj = 0; jj < 8; jj++) {
        float2 o = up2(acc8[jj]);
        int j = wr + 8*jj;
        *(float2*)&g_op[(((size_t)sp*B + b)*NN + j)*H + 2*l] = o;
    }
}

// =============== F at nodes + chebfit ===============
__global__ __launch_bounds__(256) void ffin_k(const float* __restrict__ pw,
                                              const float* __restrict__ pb) {
    __shared__ float red[NN][5];
    __shared__ float Fv[NN];
    const int b = blockIdx.x, tid = threadIdx.x;
    const int j = tid >> 2, q = tid & 3;
    float p = 0.0f;
    for (int h = q*16; h < q*16 + 16; h++) {
        float o = 0.0f;
#pragma unroll
        for (int sp = 0; sp < 8; sp++)
            o += g_op[(((size_t)sp*B + b)*NN + j)*H + h];
        p += tanhf(o) * pw[h];
    }
    red[j][q] = p;
    __syncthreads();
    if (tid < NN) Fv[tid] = pb[0] + red[tid][0] + red[tid][1] + red[tid][2] + red[tid][3];
    __syncthreads();
    if (tid < NN) {
        int n = tid;
        float a = 0.0f;
        for (int j2 = 0; j2 < NN; j2++)
            a += Fv[j2] * cospif((float)(n * (2*j2 + 1)) / (2.0f * NN));
        g_a[b*NN + n] = a * ((n == 0 ? 1.0f : 2.0f) / NN);
    }
}

// =============== out[b,t] = Clenshaw(a, u_t) ===============
__global__ __launch_bounds__(256) void final_eval(float* __restrict__ out) {
    __shared__ float as[B * NN];
    int tid = threadIdx.x;
    as[tid] = g_a[tid];
    __syncthreads();
    int i = blockIdx.x * 256 + tid;
    int b = i >> 12;
    float u = g_u[i];
    const float* a = &as[b * NN];
    float u2 = 2.0f * u;
    float bk1 = 0.0f, bk2 = 0.0f;
#pragma unroll
    for (int n = NN - 1; n >= 1; n--) {
        float bk = a[n] + u2*bk1 - bk2;
        bk2 = bk1; bk1 = bk;
    }
    out[i] = a[0] + u*bk1 - bk2;
}

// ---------------------------------------------------------------------------
extern "C" void kernel_launch(void* const* d_in, const int* in_sizes, int n_in,
                              void* d_out, int out_size) {
    const float* x   = (const float*)d_in[0];
    const float* emb = (const float*)d_in[1];
    const float* kw  = (const float*)d_in[2];
    const float* kb  = (const float*)d_in[3];
    const float* qw  = (const float*)d_in[4];
    const float* qb  = (const float*)d_in[5];
    const float* vw  = (const float*)d_in[6];
    const float* pw  = (const float*)d_in[7];
    const float* pb  = (const float*)d_in[8];
    float* out = (float*)d_out;

    cudaFuncSetAttribute(kv_pk,   cudaFuncAttributeMaxDynamicSharedMemorySize, KV_SMEM);
    cudaFuncSetAttribute(nodeo_k, cudaFuncAttributeMaxDynamicSharedMemorySize, NO_SMEM);

    prep_k<<<1, 1024>>>(x, qw, qb);
    momw_k<<<B, 512>>>();
    kv_pk<<<(B * S) / 64, 256, KV_SMEM>>>(emb, kw, kb, vw);
    p_prep<<<dim3(S / 128, B), 128>>>();
    gGrd_k<<<dim3(S / 256, B), 256>>>();
    nodeo_k<<<dim3(8, B), 256, NO_SMEM>>>();
    ffin_k<<<B, 256>>>(pw, pb);
    final_eval<<<(B * T) / 256, 256>>>(out);
}

// round 12
// speedup vs baseline: 2.9683x; 1.1772x over previous
#include <cuda_runtime.h>
#include <math.h>
#include <stdint.h>

#define B 4
#define T 4096
#define S 4096
#define E 512
#define H 64
#define RR 16
#define NN 64
#define QSCALE 0.18033688011112042
#define PI_D 3.14159265358979323846

typedef unsigned long long u64;

// ------------------ device scratch ------------------
__device__ float g_V[RR * 64];
__device__ float g_u[B * T];
__device__ float g_k[B * S * H];
__device__ float g_v[B * S * H];
__device__ float g_wq[B * NN];
__device__ float g_op[64 * B * NN * H];   // o partials per 64-s split (4 MB)
__device__ float g_F[B * NN];
__device__ float g_a[B * NN];

// ------------------ helpers ------------------
__device__ __forceinline__ void ffma2(u64& d, u64 a, u64 b) {
    asm("fma.rn.f32x2 %0, %1, %2, %0;" : "+l"(d) : "l"(a), "l"(b));
}
__device__ __forceinline__ u64 pk2(float x, float y) {
    u64 r; asm("mov.b64 %0, {%1,%2};" : "=l"(r) : "f"(x), "f"(y)); return r;
}
__device__ __forceinline__ float2 up2(u64 v) {
    float2 r; asm("mov.b64 {%0,%1}, %2;" : "=f"(r.x), "=f"(r.y) : "l"(v)); return r;
}
__device__ __forceinline__ float ex2f(float x) {
    float y; asm("ex2.approx.ftz.f32 %0, %1;" : "=f"(y) : "f"(x)); return y;
}

// =============== prep: minmax + cheb coeffs of q + u ===============
__global__ __launch_bounds__(1024) void prep_k(const float* __restrict__ x,
                                               const float* __restrict__ qw,
                                               const float* __restrict__ qb) {
    __shared__ float smn[1024], smx[1024];
    __shared__ double fd[64][17];
    __shared__ float cc[2];
    const int tid = threadIdx.x;
    float mn = 1e30f, mx = -1e30f;
    for (int i = tid; i < B * T; i += 1024) {
        float v = x[i]; mn = fminf(mn, v); mx = fmaxf(mx, v);
    }
    smn[tid] = mn; smx[tid] = mx; __syncthreads();
    for (int o = 512; o > 0; o >>= 1) {
        if (tid < o) { smn[tid] = fminf(smn[tid], smn[tid+o]); smx[tid] = fmaxf(smx[tid], smx[tid+o]); }
        __syncthreads();
    }
    if (tid == 0) {
        cc[0] = 0.5f * (smn[0] + smx[0]);
        cc[1] = 0.5f * (smx[0] - smn[0]) + 1e-6f;
    }
    __syncthreads();
    const float c = cc[0], r = cc[1];
    {
        int h = tid >> 4, j = tid & 15;
        double th = PI_D * (j + 0.5) / RR;
        fd[h][j] = QSCALE * tanh((double)qw[h] * ((double)c + (double)r * cos(th)) + (double)qb[h]);
    }
    __syncthreads();
    {
        int h = tid >> 4, m = tid & 15;
        double a = 0.0;
        for (int j = 0; j < RR; j++) a += fd[h][j] * cos(PI_D * m * (j + 0.5) / RR);
        a *= (m == 0 ? 1.0 : 2.0) / RR;
        g_V[m * 64 + h] = (float)a;
    }
    for (int i = tid; i < B * T; i += 1024) g_u[i] = (x[i] - c) / r;
}

// =============== moments + quadrature weights (per batch) ===============
__global__ __launch_bounds__(512) void momw_k() {
    __shared__ float sM[NN][17];
    __shared__ float sMM[NN];
    const int b = blockIdx.x, tid = threadIdx.x;
    const int wr = tid >> 5, l = tid & 31;
    float acc[NN];
#pragma unroll
    for (int n = 0; n < NN; n++) acc[n] = 0.0f;
    for (int t = tid; t < T; t += 512) {
        float u = g_u[b*T + t];
        float t0 = 1.0f, t1 = u;
        acc[0] += 1.0f; acc[1] += u;
#pragma unroll
        for (int n = 2; n < NN; n++) {
            float t2 = 2.0f*u*t1 - t0;
            acc[n] += t2;
            t0 = t1; t1 = t2;
        }
    }
#pragma unroll
    for (int n = 0; n < NN; n++) {
        float v = acc[n];
        v += __shfl_xor_sync(0xffffffff, v, 16);
        v += __shfl_xor_sync(0xffffffff, v, 8);
        v += __shfl_xor_sync(0xffffffff, v, 4);
        v += __shfl_xor_sync(0xffffffff, v, 2);
        v += __shfl_xor_sync(0xffffffff, v, 1);
        if (l == 0) sM[n][wr] = v;
    }
    __syncthreads();
    if (tid < NN) {
        float s = 0.0f;
#pragma unroll
        for (int w = 0; w < 16; w++) s += sM[tid][w];
        sMM[tid] = s;
    }
    __syncthreads();
    if (tid < NN) {
        int j = tid;
        float uj = cospif((j + 0.5f) / (float)NN);
        float t0 = 1.0f, t1 = uj;
        float w = sMM[0] * (1.0f/NN) + sMM[1] * t1 * (2.0f/NN);
        for (int n = 2; n < NN; n++) {
            float t2 = 2.0f*uj*t1 - t0;
            w += sMM[n] * t2 * (2.0f/NN);
            t0 = t1; t1 = t2;
        }
        g_wq[b*NN + j] = w;
    }
}

// =============== kv kernel v2: 128 rows/CTA, 16 rows/warp ===============
#define KV_EI 0                 // [64 e][130] u64 dup emb (128 r + pad)
#define KV_WP (64 * 130)        // [64 e][66] u64 col-pairs
#define KV_U64 (64 * 130 + 64 * 66)
#define KV_SMEM (KV_U64 * 8)

__global__ __launch_bounds__(256, 2) void kv_pk(const float* __restrict__ emb,
                                                const float* __restrict__ kw,
                                                const float* __restrict__ kb,
                                                const float* __restrict__ vw) {
    extern __shared__ __align__(16) u64 sm8[];
    const int r0 = blockIdx.x * 128;
    const int tid = threadIdx.x;
    const int wr = tid >> 5, l = tid & 31;

    u64 acc[16][2] = {};

    for (int e0 = 0; e0 < E; e0 += 64) {
        __syncthreads();
        // stage dup(emb): [e][r]
#pragma unroll
        for (int k = 0; k < 8; k++) {
            int idx = k * 256 + tid;
            int r = idx & 127, eg = (idx >> 7) * 4;
            float4 v = *(const float4*)(emb + (size_t)(r0 + r) * E + e0 + eg);
            sm8[KV_EI + (eg+0)*130 + r] = pk2(v.x, v.x);
            sm8[KV_EI + (eg+1)*130 + r] = pk2(v.y, v.y);
            sm8[KV_EI + (eg+2)*130 + r] = pk2(v.z, v.z);
            sm8[KV_EI + (eg+3)*130 + r] = pk2(v.w, v.w);
        }
        // stage col-pairs: [e][cp]
#pragma unroll
        for (int k = 0; k < 4; k++) {
            int idx = k * 256 + tid;
            int cp = idx & 63, eg = (idx >> 6) * 4;
            const float* w0p;
            const float* w1p;
            if (cp < 32) { w0p = kw + (size_t)(2*cp) * E; w1p = kw + (size_t)(2*cp+1) * E; }
            else         { w0p = vw + (size_t)(2*cp-64) * E; w1p = vw + (size_t)(2*cp-63) * E; }
            float4 a = *(const float4*)(w0p + e0 + eg);
            float4 bq = *(const float4*)(w1p + e0 + eg);
            sm8[KV_WP + (eg+0)*66 + cp] = pk2(a.x, bq.x);
            sm8[KV_WP + (eg+1)*66 + cp] = pk2(a.y, bq.y);
            sm8[KV_WP + (eg+2)*66 + cp] = pk2(a.z, bq.z);
            sm8[KV_WP + (eg+3)*66 + cp] = pk2(a.w, bq.w);
        }
        __syncthreads();
#pragma unroll 4
        for (int e = 0; e < 64; e++) {
            const u64* ap = sm8 + KV_EI + e*130 + 16*wr;
            ulonglong2 a01 = *(const ulonglong2*)(ap + 0);
            ulonglong2 a23 = *(const ulonglong2*)(ap + 2);
            ulonglong2 a45 = *(const ulonglong2*)(ap + 4);
            ulonglong2 a67 = *(const ulonglong2*)(ap + 6);
            ulonglong2 a89 = *(const ulonglong2*)(ap + 8);
            ulonglong2 aAB = *(const ulonglong2*)(ap + 10);
            ulonglong2 aCD = *(const ulonglong2*)(ap + 12);
            ulonglong2 aEF = *(const ulonglong2*)(ap + 14);
            u64 ar[16] = {a01.x, a01.y, a23.x, a23.y, a45.x, a45.y, a67.x, a67.y,
                          a89.x, a89.y, aAB.x, aAB.y, aCD.x, aCD.y, aEF.x, aEF.y};
            ulonglong2 bb = *(const ulonglong2*)(sm8 + KV_WP + e*66 + 2*l);
#pragma unroll
            for (int j = 0; j < 16; j++) {
                ffma2(acc[j][0], ar[j], bb.x);
                ffma2(acc[j][1], ar[j], bb.y);
            }
        }
    }
    float4 bias = make_float4(0.f, 0.f, 0.f, 0.f);
    if (l < 16) bias = *(const float4*)(kb + 4*l);
#pragma unroll
    for (int j = 0; j < 16; j++) {
        float2 c01 = up2(acc[j][0]);
        float2 c23 = up2(acc[j][1]);
        size_t row = (size_t)r0 + 16*wr + j;
        float4 o;
        if (l < 16) {
            o.x = tanhf(c01.x + bias.x); o.y = tanhf(c01.y + bias.y);
            o.z = tanhf(c23.x + bias.z); o.w = tanhf(c23.y + bias.w);
            *(float4*)(g_k + row * H + 4*l) = o;
        } else {
            o.x = tanhf(c01.x); o.y = tanhf(c01.y);
            o.z = tanhf(c23.x); o.w = tanhf(c23.y);
            *(float4*)(g_v + row * H + 4*l - 64) = o;
        }
    }
}

// =============== fused attention: P -> G -> rd -> o (per 64-s block) ===============
// byte offsets into dynamic smem
#define AT_KS 0                    // float [64 s][65] (union with vv)
#define AT_VV 0                    // u64 [32 p][66]  (16896 B)
#define AT_VS 16896                // float [16 m][64 h]
#define AT_TN 20992                // float [64 j][17]
#define AT_PF 25344                // float [16 m][68 s-pad]
#define AT_GP 29696                // u64 [64 j][34]  (s-pairs)
#define AT_WS 47104                // u64 [64] dup weights
#define AT_RD 47616                // float [64]
#define AT_SMEM 47872

__global__ __launch_bounds__(256) void attn_k() {
    extern __shared__ __align__(16) char smb[];
    float* ks  = (float*)(smb + AT_KS);
    u64*   vv  = (u64*)  (smb + AT_VV);
    float* Vs  = (float*)(smb + AT_VS);
    float* Tn  = (float*)(smb + AT_TN);
    float* Pf  = (float*)(smb + AT_PF);
    u64*   Gp  = (u64*)  (smb + AT_GP);
    u64*   wsd = (u64*)  (smb + AT_WS);
    float* rdf = (float*)(smb + AT_RD);

    const int b = blockIdx.y, sp = blockIdx.x;
    const int s0 = sp * 64;
    const int tid = threadIdx.x, wr = tid >> 5, l = tid & 31;

    // ---- phase 0: stage Vs, Tn, wsd, ks ----
#pragma unroll
    for (int k = 0; k < 4; k++) Vs[k*256 + tid] = g_V[k*256 + tid];
#pragma unroll
    for (int k = 0; k < 4; k++) {
        int i = k*256 + tid;           // 1024 = 64 j x 16 m
        int j = i >> 4, m = i & 15;
        Tn[j*17 + m] = cospif((float)(m * (2*j + 1)) / 128.0f);
    }
    if (tid < 64) {
        float w = g_wq[b*NN + tid];
        wsd[tid] = pk2(w, w);
    }
#pragma unroll
    for (int k = 0; k < 16; k++) {
        int i = k*256 + tid;           // 4096 = 64 s x 64 h
        int s = i >> 6, h = i & 63;
        ks[s*65 + h] = g_k[(size_t)(b*S + s0 + s)*H + h];
    }
    __syncthreads();

    // ---- phase 1: P[m][s] = sum_h Vs[m][h] * ks[s][h] ----
    {
        int s = tid & 63, mq = tid >> 6;
        float pacc[4] = {};
#pragma unroll
        for (int h = 0; h < 64; h++) {
            float kx = ks[s*65 + h];
#pragma unroll
            for (int mi = 0; mi < 4; mi++) pacc[mi] += Vs[(4*mq + mi)*64 + h] * kx;
        }
#pragma unroll
        for (int mi = 0; mi < 4; mi++) Pf[(4*mq + mi)*68 + s] = pacc[mi];
    }
    __syncthreads();

    // ---- phase 2: G[j][s-pairs] = exp2( sum_m Tn[j][m] * P[m][s] ) ----
    {
        int j = tid >> 2, sq = tid & 3;
        u64 am[16];
#pragma unroll
        for (int m = 0; m < 16; m++) {
            float t = Tn[j*17 + m];
            am[m] = pk2(t, t);
        }
#pragma unroll
        for (int i = 0; i < 8; i++) {
            int p = sq + 4*i;
            u64 lacc = 0;
#pragma unroll
            for (int m = 0; m < 16; m++)
                ffma2(lacc, am[m], *(const u64*)&Pf[m*68 + 2*p]);
            float2 f = up2(lacc);
            Gp[j*34 + p] = pk2(ex2f(f.x), ex2f(f.y));
        }
    }
    __syncthreads();

    // ---- phase 3: rd[s] = 1 / sum_j w_j G[j][s] ----
    if (tid < 32) {
        int p = tid;
        u64 dacc = 0;
#pragma unroll
        for (int j = 0; j < 64; j++) ffma2(dacc, wsd[j], Gp[j*34 + p]);
        float2 d2 = up2(dacc);
        rdf[2*p]   = 1.0f / d2.x;
        rdf[2*p+1] = 1.0f / d2.y;
    }
    __syncthreads();

    // ---- phase 4: stage vv[p][h] = (v[2p][h]*rd0, v[2p+1][h]*rd1) (aliases ks) ----
    {
        int p = tid >> 3, hq = tid & 7;
        size_t rv = (size_t)(b*S + s0 + 2*p) * H;
        float rd0 = rdf[2*p], rd1 = rdf[2*p+1];
#pragma unroll
        for (int i = 0; i < 8; i++) {
            int h = hq + 8*i;
            vv[p*66 + h] = pk2(g_v[rv + h] * rd0, g_v[rv + H + h] * rd1);
        }
    }
    __syncthreads();

    // ---- phase 5: o[j][h] += sum_s G[j][s] v'[s][h] (s-pair packed) ----
    u64 acc[8][2] = {};
#pragma unroll 4
    for (int p = 0; p < 32; p++) {
        u64 b0 = vv[p*66 + l];
        u64 b1 = vv[p*66 + 32 + l];
#pragma unroll
        for (int jj = 0; jj < 8; jj++) {
            u64 a = Gp[(8*wr + jj)*34 + p];
            ffma2(acc[jj][0], a, b0);
            ffma2(acc[jj][1], a, b1);
        }
    }
#pragma unroll
    for (int jj = 0; jj < 8; jj++) {
        int j = 8*wr + jj;
        float2 f0 = up2(acc[jj][0]);
        float2 f1 = up2(acc[jj][1]);
        size_t base = ((size_t)(sp*B + b)*NN + j)*H;
        g_op[base + l]      = f0.x + f0.y;
        g_op[base + 32 + l] = f1.x + f1.y;
    }
}

// =============== F[b,j] = pb + sum_h pw[h] tanh( sum_sp o_partial ) ===============
__global__ __launch_bounds__(64) void ffin_k(const float* __restrict__ pw,
                                             const float* __restrict__ pb) {
    __shared__ float rs[2];
    const int b = blockIdx.y, j = blockIdx.x, h = threadIdx.x;
    float o = 0.0f;
#pragma unroll 8
    for (int sp = 0; sp < 64; sp++)
        o += g_op[((size_t)(sp*B + b)*NN + j)*H + h];
    float p = tanhf(o) * pw[h];
#pragma unroll
    for (int d = 16; d; d >>= 1) p += __shfl_xor_sync(0xffffffff, p, d);
    if ((h & 31) == 0) rs[h >> 5] = p;
    __syncthreads();
    if (h == 0) g_F[b*NN + j] = pb[0] + rs[0] + rs[1];
}

// =============== chebfit of F ===============
__global__ void cheb_k() {
    int tid = threadIdx.x;              // 256 = B*NN
    int b = tid >> 6, n = tid & 63;
    float a = 0.0f;
    for (int j = 0; j < NN; j++)
        a += g_F[b*NN + j] * cospif((float)(n * (2*j + 1)) / (2.0f * NN));
    g_a[tid] = a * ((n == 0 ? 1.0f : 2.0f) / NN);
}

// =============== out[b,t] = Clenshaw(a, u_t) ===============
__global__ __launch_bounds__(256) void final_eval(float* __restrict__ out) {
    __shared__ float as[B * NN];
    int tid = threadIdx.x;
    as[tid] = g_a[tid];
    __syncthreads();
    int i = blockIdx.x * 256 + tid;
    int b = i >> 12;
    float u = g_u[i];
    const float* a = &as[b * NN];
    float u2 = 2.0f * u;
    float bk1 = 0.0f, bk2 = 0.0f;
#pragma unroll
    for (int n = NN - 1; n >= 1; n--) {
        float bk = a[n] + u2*bk1 - bk2;
        bk2 = bk1; bk1 = bk;
    }
    out[i] = a[0] + u*bk1 - bk2;
}

// ---------------------------------------------------------------------------
extern "C" void kernel_launch(void* const* d_in, const int* in_sizes, int n_in,
                              void* d_out, int out_size) {
    const float* x   = (const float*)d_in[0];
    const float* emb = (const float*)d_in[1];
    const float* kw  = (const float*)d_in[2];
    const float* kb  = (const float*)d_in[3];
    const float* qw  = (const float*)d_in[4];
    const float* qb  = (const float*)d_in[5];
    const float* vw  = (const float*)d_in[6];
    const float* pw  = (const float*)d_in[7];
    const float* pb  = (const float*)d_in[8];
    float* out = (float*)d_out;

    cudaFuncSetAttribute(kv_pk,  cudaFuncAttributeMaxDynamicSharedMemorySize, KV_SMEM);
    cudaFuncSetAttribute(attn_k, cudaFuncAttributeMaxDynamicSharedMemorySize, AT_SMEM);

    prep_k<<<1, 1024>>>(x, qw, qb);
    momw_k<<<B, 512>>>();
    kv_pk<<<(B * S) / 128, 256, KV_SMEM>>>(emb, kw, kb, vw);
    attn_k<<<dim3(64, B), 256, AT_SMEM>>>();
    ffin_k<<<dim3(NN, B), 64>>>(pw, pb);
    cheb_k<<<1, 256>>>();
    final_eval<<<(B * T) / 256, 256>>>(out);
}